// round 2
// baseline (speedup 1.0000x reference)
#include <cuda_runtime.h>

// Problem constants (fixed by the dataset)
#define INDIM 256
#define HID   128     // H * F1
#define NH    4
#define FD    32
#define C2    40      // classes
#define C2P   64      // padded cols for gemm2
#define NMAXN 100000
#define EMAXE 1600000

// -------- scratch (static device globals; no allocations anywhere) --------
__device__ float g_h1  [(size_t)NMAXN * HID];   // layer1 projection
__device__ float g_out1[(size_t)NMAXN * HID];   // layer1 aggregation -> ELU -> x
__device__ float g_h2  [(size_t)NMAXN * C2];    // layer2 projection
__device__ float g_el1 [NMAXN * NH];
__device__ float g_er1 [NMAXN * NH];
__device__ float g_m1  [NMAXN * NH];
__device__ float g_s1  [NMAXN * NH];
__device__ float g_el2 [NMAXN];
__device__ float g_er2 [NMAXN];
__device__ float g_m2  [NMAXN];
__device__ float g_s2  [NMAXN];
__device__ float g_e1  [(size_t)EMAXE * NH];    // edge scores -> exp'd scores
__device__ float g_e2  [EMAXE];
__device__ float g_W2p [HID * C2P];             // zero-padded W2 (128x64)

// -------- helpers --------
__device__ __forceinline__ float lrelu(float v) { return v > 0.f ? v : 0.2f * v; }

// exact float atomic max via signed(int)-max / unsigned-min trick
__device__ __forceinline__ void atomicMaxF(float* addr, float v) {
    if (v >= 0.f) atomicMax((int*)addr, __float_as_int(v));
    else          atomicMin((unsigned int*)addr, __float_as_uint(v));
}

// vectorized global reduction (sm_90+): 4 floats, 1 instruction
__device__ __forceinline__ void redAdd4(float* p, float x, float y, float z, float w) {
    asm volatile("red.global.add.v4.f32 [%0], {%1, %2, %3, %4};"
                 :: "l"(p), "f"(x), "f"(y), "f"(z), "f"(w) : "memory");
}

// ============================================================================
// Tiled GEMM: C[nrows x NCREAL] = A[nrows x K] * W[K x NC] (W padded to NC)
// BM=64, BK=32, 256 threads, each thread: 8 rows x (NC/32) cols
// ============================================================================
template <int K, int NC, int NCREAL>
__global__ __launch_bounds__(256)
void gemm_tiled(const float* __restrict__ A, const float* __restrict__ W,
                float* __restrict__ C, int nrows, int ostride)
{
    constexpr int CPT = NC / 32;   // cols per thread (4 for NC=128, 2 for NC=64)
    __shared__ float fsh[64][32];
    __shared__ float wsh[32][NC];

    const int tid = threadIdx.x;
    const int r0  = blockIdx.x * 64;
    const int cx  = tid & 31;      // thread-col group (lane)
    const int ry  = tid >> 5;      // warp id -> row group

    float acc[8][CPT];
#pragma unroll
    for (int i = 0; i < 8; i++)
#pragma unroll
        for (int j = 0; j < CPT; j++) acc[i][j] = 0.f;

    for (int kt = 0; kt < K; kt += 32) {
        // load 64x32 A tile (float4, guarded rows)
#pragma unroll
        for (int i = 0; i < 2; i++) {
            int idx = tid + i * 256;
            int r = idx >> 3, kq = idx & 7;
            int row = r0 + r;
            float4 v = make_float4(0.f, 0.f, 0.f, 0.f);
            if (row < nrows)
                v = *(const float4*)(A + (size_t)row * K + kt + kq * 4);
            *(float4*)(&fsh[r][kq * 4]) = v;
        }
        // load 32xNC W tile
#pragma unroll
        for (int i = 0; i < CPT; i++) {
            int idx = tid + i * 256;
            int kr = idx / (NC / 4), cq = idx % (NC / 4);
            *(float4*)(&wsh[kr][cq * 4]) =
                *(const float4*)(W + (size_t)(kt + kr) * NC + cq * 4);
        }
        __syncthreads();

#pragma unroll
        for (int k = 0; k < 32; k++) {
            float w[CPT];
            if constexpr (CPT == 4) {
                float4 wv = *(const float4*)(&wsh[k][cx * 4]);
                w[0] = wv.x; w[1] = wv.y; w[2] = wv.z; w[3] = wv.w;
            } else {
                float2 wv = *(const float2*)(&wsh[k][cx * 2]);
                w[0] = wv.x; w[1] = wv.y;
            }
#pragma unroll
            for (int i = 0; i < 8; i++) {
                float f = fsh[ry * 8 + i][k];   // uniform in warp -> broadcast
#pragma unroll
                for (int j = 0; j < CPT; j++) acc[i][j] += f * w[j];
            }
        }
        __syncthreads();
    }

#pragma unroll
    for (int i = 0; i < 8; i++) {
        int row = r0 + ry * 8 + i;
        if (row >= nrows) continue;
#pragma unroll
        for (int j = 0; j < CPT; j++) {
            int col = cx * CPT + j;
            if (col < NCREAL)
                C[(size_t)row * ostride + col] = acc[i][j];
        }
    }
}

// ============================================================================
// init / pack kernels
// ============================================================================
__global__ void init_scratch(int n)
{
    int i = blockIdx.x * blockDim.x + threadIdx.x;
    int tot = n * HID;
    if (i < tot)  g_out1[i] = 0.f;
    if (i < n * NH) { g_s1[i] = 0.f; g_m1[i] = __int_as_float(0xff800000); }
    if (i < n)      { g_s2[i] = 0.f; g_m2[i] = __int_as_float(0xff800000); }
}

__global__ void zero_out(float* p, int n)
{
    int i = blockIdx.x * blockDim.x + threadIdx.x;
    if (i < n) p[i] = 0.f;
}

__global__ void pack_W2(const float* __restrict__ W2)
{
    int i = blockIdx.x * blockDim.x + threadIdx.x;
    if (i >= HID * C2P) return;
    int k = i / C2P, c = i % C2P;
    g_W2p[i] = (c < C2) ? W2[k * C2 + c] : 0.f;
}

// ============================================================================
// per-node attention halves
// ============================================================================
__global__ void elr1_kernel(const float* __restrict__ al, const float* __restrict__ ar, int n)
{
    __shared__ float sal[HID], sar[HID];
    if (threadIdx.x < HID) { sal[threadIdx.x] = al[threadIdx.x]; sar[threadIdx.x] = ar[threadIdx.x]; }
    __syncthreads();
    int i = blockIdx.x * blockDim.x + threadIdx.x;
    if (i >= n) return;
    const float* hrow = g_h1 + (size_t)i * HID;
    float el[NH] = {0.f, 0.f, 0.f, 0.f}, er[NH] = {0.f, 0.f, 0.f, 0.f};
#pragma unroll
    for (int k = 0; k < HID; k++) {
        float v = hrow[k];
        int h = k >> 5;
        el[h] += v * sal[k];
        er[h] += v * sar[k];
    }
    *(float4*)(g_el1 + (size_t)i * 4) = make_float4(el[0], el[1], el[2], el[3]);
    *(float4*)(g_er1 + (size_t)i * 4) = make_float4(er[0], er[1], er[2], er[3]);
}

__global__ void elr2_kernel(const float* __restrict__ al, const float* __restrict__ ar, int n)
{
    __shared__ float sal[C2], sar[C2];
    if (threadIdx.x < C2) { sal[threadIdx.x] = al[threadIdx.x]; sar[threadIdx.x] = ar[threadIdx.x]; }
    __syncthreads();
    int i = blockIdx.x * blockDim.x + threadIdx.x;
    if (i >= n) return;
    const float* hrow = g_h2 + (size_t)i * C2;
    float el = 0.f, er = 0.f;
#pragma unroll
    for (int k = 0; k < C2; k++) {
        float v = hrow[k];
        el += v * sal[k];
        er += v * sar[k];
    }
    g_el2[i] = el;
    g_er2[i] = er;
}

// ============================================================================
// edge kernels, layer 1 (4 heads)
// ============================================================================
__global__ void score1_kernel(const int* __restrict__ src, const int* __restrict__ dst, int e)
{
    int i = blockIdx.x * blockDim.x + threadIdx.x;
    if (i >= e) return;
    int s = src[i], d = dst[i];
    float4 a = *(const float4*)(g_el1 + (size_t)s * 4);
    float4 b = *(const float4*)(g_er1 + (size_t)d * 4);
    float4 v;
    v.x = lrelu(a.x + b.x); v.y = lrelu(a.y + b.y);
    v.z = lrelu(a.z + b.z); v.w = lrelu(a.w + b.w);
    *(float4*)(g_e1 + (size_t)i * 4) = v;
    atomicMaxF(&g_m1[d * 4 + 0], v.x);
    atomicMaxF(&g_m1[d * 4 + 1], v.y);
    atomicMaxF(&g_m1[d * 4 + 2], v.z);
    atomicMaxF(&g_m1[d * 4 + 3], v.w);
}

__global__ void expsum1_kernel(const int* __restrict__ dst, int e)
{
    int i = blockIdx.x * blockDim.x + threadIdx.x;
    if (i >= e) return;
    int d = dst[i];
    float4 v = *(const float4*)(g_e1 + (size_t)i * 4);
    float4 m = *(const float4*)(g_m1 + (size_t)d * 4);
    float4 ee;
    ee.x = __expf(v.x - m.x); ee.y = __expf(v.y - m.y);
    ee.z = __expf(v.z - m.z); ee.w = __expf(v.w - m.w);
    *(float4*)(g_e1 + (size_t)i * 4) = ee;
    redAdd4(&g_s1[d * 4], ee.x, ee.y, ee.z, ee.w);
}

// weighted scatter-add: one thread per (edge, head), vector reductions
__global__ void agg1_kernel(const int* __restrict__ src, const int* __restrict__ dst, int e)
{
    int t = blockIdx.x * blockDim.x + threadIdx.x;
    if (t >= e * NH) return;
    int i = t >> 2, h = t & 3;
    int s = src[i], d = dst[i];
    float alpha = g_e1[(size_t)i * 4 + h] / g_s1[d * 4 + h];
    const float* hp = g_h1 + (size_t)s * HID + h * FD;
    float*       op = g_out1 + (size_t)d * HID + h * FD;
#pragma unroll
    for (int q = 0; q < 8; q++) {
        float4 v = *(const float4*)(hp + q * 4);
        redAdd4(op + q * 4, alpha * v.x, alpha * v.y, alpha * v.z, alpha * v.w);
    }
}

__global__ void elu_kernel(const float* __restrict__ b1, int n)
{
    int i = blockIdx.x * blockDim.x + threadIdx.x;
    if (i >= n * HID) return;
    float v = g_out1[i] + b1[i & (HID - 1)];
    g_out1[i] = v > 0.f ? v : (__expf(v) - 1.f);
}

// ============================================================================
// edge kernels, layer 2 (1 head, C=40)
// ============================================================================
__global__ void score2_kernel(const int* __restrict__ src, const int* __restrict__ dst, int e)
{
    int i = blockIdx.x * blockDim.x + threadIdx.x;
    if (i >= e) return;
    int s = src[i], d = dst[i];
    float v = lrelu(g_el2[s] + g_er2[d]);
    g_e2[i] = v;
    atomicMaxF(&g_m2[d], v);
}

__global__ void expsum2_kernel(const int* __restrict__ dst, int e)
{
    int i = blockIdx.x * blockDim.x + threadIdx.x;
    if (i >= e) return;
    int d = dst[i];
    float ee = __expf(g_e2[i] - g_m2[d]);
    g_e2[i] = ee;
    atomicAdd(&g_s2[d], ee);
}

__global__ void agg2_kernel(const int* __restrict__ src, const int* __restrict__ dst,
                            float* __restrict__ out, int e)
{
    int i = blockIdx.x * blockDim.x + threadIdx.x;
    if (i >= e) return;
    int s = src[i], d = dst[i];
    float alpha = g_e2[i] / g_s2[d];
    const float* hp = g_h2 + (size_t)s * C2;
    float*       op = out + (size_t)d * C2;
#pragma unroll
    for (int q = 0; q < 10; q++) {
        float4 v = *(const float4*)(hp + q * 4);
        redAdd4(op + q * 4, alpha * v.x, alpha * v.y, alpha * v.z, alpha * v.w);
    }
}

__global__ void bias2_kernel(float* __restrict__ out, const float* __restrict__ b2, int n)
{
    int i = blockIdx.x * blockDim.x + threadIdx.x;
    if (i >= n * C2) return;
    out[i] += b2[i % C2];
}

// ============================================================================
// launch
// ============================================================================
extern "C" void kernel_launch(void* const* d_in, const int* in_sizes, int n_in,
                              void* d_out, int out_size)
{
    const float* feat = (const float*)d_in[0];
    const int*   src  = (const int*)  d_in[1];
    const int*   dst  = (const int*)  d_in[2];
    const float* W1   = (const float*)d_in[3];
    const float* al1  = (const float*)d_in[4];
    const float* ar1  = (const float*)d_in[5];
    const float* b1   = (const float*)d_in[6];
    const float* W2   = (const float*)d_in[7];
    const float* al2  = (const float*)d_in[8];
    const float* ar2  = (const float*)d_in[9];
    const float* b2   = (const float*)d_in[10];
    float* out = (float*)d_out;

    const int n = in_sizes[0] / INDIM;   // 100000
    const int e = in_sizes[1];           // 1600000

    // R1 bug fix: __device__ symbols passed as host-side kernel args are NOT
    // device pointers. Resolve them properly (non-stream API, capture-safe).
    float *p_h1 = 0, *p_out1 = 0, *p_h2 = 0, *p_W2p = 0;
    cudaGetSymbolAddress((void**)&p_h1,   g_h1);
    cudaGetSymbolAddress((void**)&p_out1, g_out1);
    cudaGetSymbolAddress((void**)&p_h2,   g_h2);
    cudaGetSymbolAddress((void**)&p_W2p,  g_W2p);

    const int TB = 256;
    // init
    init_scratch<<<(n * HID + TB - 1) / TB, TB>>>(n);
    zero_out<<<(n * C2 + TB - 1) / TB, TB>>>(out, n * C2);
    pack_W2<<<(HID * C2P + TB - 1) / TB, TB>>>(W2);

    // ---- layer 1 ----
    gemm_tiled<INDIM, HID, HID><<<(n + 63) / 64, 256>>>(feat, W1, p_h1, n, HID);
    elr1_kernel<<<(n + 127) / 128, 128>>>(al1, ar1, n);
    score1_kernel<<<(e + TB - 1) / TB, TB>>>(src, dst, e);
    expsum1_kernel<<<(e + TB - 1) / TB, TB>>>(dst, e);
    agg1_kernel<<<(e * NH + TB - 1) / TB, TB>>>(src, dst, e);
    elu_kernel<<<(n * HID + TB - 1) / TB, TB>>>(b1, n);

    // ---- layer 2 ----
    gemm_tiled<HID, C2P, C2><<<(n + 63) / 64, 256>>>(p_out1, p_W2p, p_h2, n, C2);
    elr2_kernel<<<(n + 127) / 128, 128>>>(al2, ar2, n);
    score2_kernel<<<(e + TB - 1) / TB, TB>>>(src, dst, e);
    expsum2_kernel<<<(e + TB - 1) / TB, TB>>>(dst, e);
    agg2_kernel<<<(e + TB - 1) / TB, TB>>>(src, dst, out, e);
    bias2_kernel<<<(n * C2 + TB - 1) / TB, TB>>>(out, b2, n);
}

// round 3
// speedup vs baseline: 1.9652x; 1.9652x over previous
#include <cuda_runtime.h>

// Problem constants (fixed by the dataset)
#define INDIM 256
#define HID   128     // H * F1
#define NH    4
#define FD    32
#define C2    40      // classes
#define C2P   64      // padded cols for gemm2
#define NMAXN 100000
#define EMAXE 1600000

#define NEG_INF __int_as_float(0xff800000)

// -------- scratch (static device globals; no allocations anywhere) --------
__device__ float g_h1  [(size_t)NMAXN * HID];   // layer1 projection
__device__ float g_out1[(size_t)NMAXN * HID];   // layer1 output (post-ELU)
__device__ float g_h2  [(size_t)NMAXN * C2];    // layer2 projection
__device__ float g_el1 [NMAXN * NH];
__device__ float g_er1 [NMAXN * NH];
__device__ float g_el2 [NMAXN];
__device__ float g_er2 [NMAXN];
__device__ float g_e1  [(size_t)EMAXE * NH];    // per-edge scores (CSR order)
__device__ float g_e2  [EMAXE];
__device__ float g_W2p [HID * C2P];             // zero-padded W2 (128x64)
// CSR by dst
__device__ int   g_deg [NMAXN];
__device__ int   g_off [NMAXN + 1];
__device__ int   g_cur [NMAXN];
__device__ int   g_part[256];                   // block partial sums for scan
__device__ int   g_csr_src[EMAXE];

// -------- helpers --------
__device__ __forceinline__ float lrelu(float v) { return v > 0.f ? v : 0.2f * v; }
__device__ __forceinline__ float elu(float v)   { return v > 0.f ? v : (__expf(v) - 1.f); }

// ============================================================================
// Tiled GEMM (unchanged from R2 — known good)
// ============================================================================
template <int K, int NC, int NCREAL>
__global__ __launch_bounds__(256)
void gemm_tiled(const float* __restrict__ A, const float* __restrict__ W,
                float* __restrict__ C, int nrows, int ostride)
{
    constexpr int CPT = NC / 32;
    __shared__ float fsh[64][32];
    __shared__ float wsh[32][NC];

    const int tid = threadIdx.x;
    const int r0  = blockIdx.x * 64;
    const int cx  = tid & 31;
    const int ry  = tid >> 5;

    float acc[8][CPT];
#pragma unroll
    for (int i = 0; i < 8; i++)
#pragma unroll
        for (int j = 0; j < CPT; j++) acc[i][j] = 0.f;

    for (int kt = 0; kt < K; kt += 32) {
#pragma unroll
        for (int i = 0; i < 2; i++) {
            int idx = tid + i * 256;
            int r = idx >> 3, kq = idx & 7;
            int row = r0 + r;
            float4 v = make_float4(0.f, 0.f, 0.f, 0.f);
            if (row < nrows)
                v = *(const float4*)(A + (size_t)row * K + kt + kq * 4);
            *(float4*)(&fsh[r][kq * 4]) = v;
        }
#pragma unroll
        for (int i = 0; i < CPT; i++) {
            int idx = tid + i * 256;
            int kr = idx / (NC / 4), cq = idx % (NC / 4);
            *(float4*)(&wsh[kr][cq * 4]) =
                *(const float4*)(W + (size_t)(kt + kr) * NC + cq * 4);
        }
        __syncthreads();

#pragma unroll
        for (int k = 0; k < 32; k++) {
            float w[CPT];
            if constexpr (CPT == 4) {
                float4 wv = *(const float4*)(&wsh[k][cx * 4]);
                w[0] = wv.x; w[1] = wv.y; w[2] = wv.z; w[3] = wv.w;
            } else {
                float2 wv = *(const float2*)(&wsh[k][cx * 2]);
                w[0] = wv.x; w[1] = wv.y;
            }
#pragma unroll
            for (int i = 0; i < 8; i++) {
                float f = fsh[ry * 8 + i][k];
#pragma unroll
                for (int j = 0; j < CPT; j++) acc[i][j] += f * w[j];
            }
        }
        __syncthreads();
    }

#pragma unroll
    for (int i = 0; i < 8; i++) {
        int row = r0 + ry * 8 + i;
        if (row >= nrows) continue;
#pragma unroll
        for (int j = 0; j < CPT; j++) {
            int col = cx * CPT + j;
            if (col < NCREAL)
                C[(size_t)row * ostride + col] = acc[i][j];
        }
    }
}

// ============================================================================
// CSR build: count -> block scan -> top scan -> add -> scatter
// ============================================================================
__global__ void zero_deg(int n)
{
    int i = blockIdx.x * blockDim.x + threadIdx.x;
    if (i < n) g_deg[i] = 0;
}

__global__ void count_kernel(const int* __restrict__ dst, int e)
{
    int i = blockIdx.x * blockDim.x + threadIdx.x;
    if (i < e) atomicAdd(&g_deg[dst[i]], 1);
}

__global__ __launch_bounds__(1024)
void scan_local(int n)
{
    __shared__ int sh[1024];
    int t = threadIdx.x;
    int i = blockIdx.x * 1024 + t;
    int val = (i < n) ? g_deg[i] : 0;
    sh[t] = val;
    __syncthreads();
#pragma unroll
    for (int d = 1; d < 1024; d <<= 1) {
        int x = (t >= d) ? sh[t - d] : 0;
        __syncthreads();
        sh[t] += x;
        __syncthreads();
    }
    if (i < n) g_off[i] = sh[t] - val;        // local exclusive
    if (t == 1023) g_part[blockIdx.x] = sh[1023];
}

__global__ void scan_part(int nblk, int n)
{
    if (threadIdx.x != 0 || blockIdx.x != 0) return;
    int run = 0;
    for (int b = 0; b < nblk; b++) {
        int v = g_part[b];
        g_part[b] = run;
        run += v;
    }
    g_off[n] = run;
}

__global__ void add_part(int n)
{
    int i = blockIdx.x * blockDim.x + threadIdx.x;
    if (i >= n) return;
    int o = g_off[i] + g_part[i >> 10];
    g_off[i] = o;
    g_cur[i] = o;
}

__global__ void scatter_kernel(const int* __restrict__ src, const int* __restrict__ dst, int e)
{
    int i = blockIdx.x * blockDim.x + threadIdx.x;
    if (i >= e) return;
    int d = dst[i];
    int pos = atomicAdd(&g_cur[d], 1);
    g_csr_src[pos] = src[i];
}

// ============================================================================
// misc
// ============================================================================
__global__ void pack_W2(const float* __restrict__ W2)
{
    int i = blockIdx.x * blockDim.x + threadIdx.x;
    if (i >= HID * C2P) return;
    int k = i / C2P, c = i % C2P;
    g_W2p[i] = (c < C2) ? W2[k * C2 + c] : 0.f;
}

__global__ void elr1_kernel(const float* __restrict__ al, const float* __restrict__ ar, int n)
{
    __shared__ float sal[HID], sar[HID];
    if (threadIdx.x < HID) { sal[threadIdx.x] = al[threadIdx.x]; sar[threadIdx.x] = ar[threadIdx.x]; }
    __syncthreads();
    int i = blockIdx.x * blockDim.x + threadIdx.x;
    if (i >= n) return;
    const float* hrow = g_h1 + (size_t)i * HID;
    float el[NH] = {0.f, 0.f, 0.f, 0.f}, er[NH] = {0.f, 0.f, 0.f, 0.f};
#pragma unroll
    for (int k = 0; k < HID; k++) {
        float v = hrow[k];
        int h = k >> 5;
        el[h] += v * sal[k];
        er[h] += v * sar[k];
    }
    *(float4*)(g_el1 + (size_t)i * 4) = make_float4(el[0], el[1], el[2], el[3]);
    *(float4*)(g_er1 + (size_t)i * 4) = make_float4(er[0], er[1], er[2], er[3]);
}

__global__ void elr2_kernel(const float* __restrict__ al, const float* __restrict__ ar, int n)
{
    __shared__ float sal[C2], sar[C2];
    if (threadIdx.x < C2) { sal[threadIdx.x] = al[threadIdx.x]; sar[threadIdx.x] = ar[threadIdx.x]; }
    __syncthreads();
    int i = blockIdx.x * blockDim.x + threadIdx.x;
    if (i >= n) return;
    const float* hrow = g_h2 + (size_t)i * C2;
    float el = 0.f, er = 0.f;
#pragma unroll
    for (int k = 0; k < C2; k++) {
        float v = hrow[k];
        el += v * sal[k];
        er += v * sar[k];
    }
    g_el2[i] = el;
    g_er2[i] = er;
}

// ============================================================================
// Layer 1: warp per node — softmax + aggregation, no atomics
// lane covers feature slice [lane*4, lane*4+4); head = lane>>3
// ============================================================================
__global__ __launch_bounds__(256)
void gat1_kernel(const float* __restrict__ b1, int n)
{
    int node = (blockIdx.x * blockDim.x + threadIdx.x) >> 5;
    int lane = threadIdx.x & 31;
    if (node >= n) return;

    int off = g_off[node];
    int deg = g_off[node + 1] - off;

    float4 erd = *(const float4*)(g_er1 + (size_t)node * 4);

    // ---- pass A: scores -> g_e1 (CSR order), warp max ----
    float4 mx = make_float4(NEG_INF, NEG_INF, NEG_INF, NEG_INF);
    for (int base = 0; base < deg; base += 32) {
        int j = base + lane;
        if (j < deg) {
            int s = g_csr_src[off + j];
            float4 a = *(const float4*)(g_el1 + (size_t)s * 4);
            float4 e4;
            e4.x = lrelu(a.x + erd.x); e4.y = lrelu(a.y + erd.y);
            e4.z = lrelu(a.z + erd.z); e4.w = lrelu(a.w + erd.w);
            *(float4*)(g_e1 + (size_t)(off + j) * 4) = e4;
            mx.x = fmaxf(mx.x, e4.x); mx.y = fmaxf(mx.y, e4.y);
            mx.z = fmaxf(mx.z, e4.z); mx.w = fmaxf(mx.w, e4.w);
        }
    }
#pragma unroll
    for (int o = 16; o; o >>= 1) {
        mx.x = fmaxf(mx.x, __shfl_xor_sync(0xffffffffu, mx.x, o));
        mx.y = fmaxf(mx.y, __shfl_xor_sync(0xffffffffu, mx.y, o));
        mx.z = fmaxf(mx.z, __shfl_xor_sync(0xffffffffu, mx.z, o));
        mx.w = fmaxf(mx.w, __shfl_xor_sync(0xffffffffu, mx.w, o));
    }

    // ---- pass B: exp -> g_e1, warp sum ----
    float4 sm = make_float4(0.f, 0.f, 0.f, 0.f);
    for (int base = 0; base < deg; base += 32) {
        int j = base + lane;
        if (j < deg) {
            float4 e4 = *(const float4*)(g_e1 + (size_t)(off + j) * 4);
            e4.x = __expf(e4.x - mx.x); e4.y = __expf(e4.y - mx.y);
            e4.z = __expf(e4.z - mx.z); e4.w = __expf(e4.w - mx.w);
            *(float4*)(g_e1 + (size_t)(off + j) * 4) = e4;
            sm.x += e4.x; sm.y += e4.y; sm.z += e4.z; sm.w += e4.w;
        }
    }
#pragma unroll
    for (int o = 16; o; o >>= 1) {
        sm.x += __shfl_xor_sync(0xffffffffu, sm.x, o);
        sm.y += __shfl_xor_sync(0xffffffffu, sm.y, o);
        sm.z += __shfl_xor_sync(0xffffffffu, sm.z, o);
        sm.w += __shfl_xor_sync(0xffffffffu, sm.w, o);
    }

    int head = lane >> 3;
    float invh = 0.f;
    if (deg > 0) {
        float s = (head == 0) ? sm.x : (head == 1) ? sm.y : (head == 2) ? sm.z : sm.w;
        invh = 1.f / s;
    }

    // ---- pass C: weighted gather-accumulate ----
    float4 acc = make_float4(0.f, 0.f, 0.f, 0.f);
    for (int base = 0; base < deg; base += 32) {
        int j = base + lane;
        int cnt = min(32, deg - base);
        int s = 0;
        float4 ee = make_float4(0.f, 0.f, 0.f, 0.f);
        if (j < deg) {
            s = g_csr_src[off + j];
            ee = *(const float4*)(g_e1 + (size_t)(off + j) * 4);
        }
        for (int q = 0; q < cnt; q++) {
            int   sq = __shfl_sync(0xffffffffu, s, q);
            float a0 = __shfl_sync(0xffffffffu, ee.x, q);
            float a1 = __shfl_sync(0xffffffffu, ee.y, q);
            float a2 = __shfl_sync(0xffffffffu, ee.z, q);
            float a3 = __shfl_sync(0xffffffffu, ee.w, q);
            float a  = ((head == 0) ? a0 : (head == 1) ? a1 : (head == 2) ? a2 : a3) * invh;
            float4 hv = *(const float4*)(g_h1 + (size_t)sq * HID + lane * 4);
            acc.x += a * hv.x; acc.y += a * hv.y;
            acc.z += a * hv.z; acc.w += a * hv.w;
        }
    }

    // ---- epilogue: bias + ELU, direct store ----
    float4 bb = *(const float4*)(b1 + lane * 4);
    float4 o;
    o.x = elu(acc.x + bb.x); o.y = elu(acc.y + bb.y);
    o.z = elu(acc.z + bb.z); o.w = elu(acc.w + bb.w);
    *(float4*)(g_out1 + (size_t)node * HID + lane * 4) = o;
}

// ============================================================================
// Layer 2: warp per node (1 head, C=40); lane covers f=lane and f=32+lane (lane<8)
// ============================================================================
__global__ __launch_bounds__(256)
void gat2_kernel(float* __restrict__ out, const float* __restrict__ b2, int n)
{
    int node = (blockIdx.x * blockDim.x + threadIdx.x) >> 5;
    int lane = threadIdx.x & 31;
    if (node >= n) return;

    int off = g_off[node];
    int deg = g_off[node + 1] - off;

    float erd = g_er2[node];

    // pass A: score + max
    float mx = NEG_INF;
    for (int base = 0; base < deg; base += 32) {
        int j = base + lane;
        if (j < deg) {
            int s = g_csr_src[off + j];
            float e = lrelu(g_el2[s] + erd);
            g_e2[off + j] = e;
            mx = fmaxf(mx, e);
        }
    }
#pragma unroll
    for (int o = 16; o; o >>= 1)
        mx = fmaxf(mx, __shfl_xor_sync(0xffffffffu, mx, o));

    // pass B: exp + sum
    float sm = 0.f;
    for (int base = 0; base < deg; base += 32) {
        int j = base + lane;
        if (j < deg) {
            float ee = __expf(g_e2[off + j] - mx);
            g_e2[off + j] = ee;
            sm += ee;
        }
    }
#pragma unroll
    for (int o = 16; o; o >>= 1)
        sm += __shfl_xor_sync(0xffffffffu, sm, o);
    float inv = (deg > 0) ? 1.f / sm : 0.f;

    // pass C: gather-accumulate (40 features: lane + [lane<8 -> 32+lane])
    float acc0 = 0.f, acc1 = 0.f;
    for (int base = 0; base < deg; base += 32) {
        int j = base + lane;
        int cnt = min(32, deg - base);
        int s = 0; float ee = 0.f;
        if (j < deg) {
            s = g_csr_src[off + j];
            ee = g_e2[off + j];
        }
        for (int q = 0; q < cnt; q++) {
            int   sq = __shfl_sync(0xffffffffu, s, q);
            float a  = __shfl_sync(0xffffffffu, ee, q) * inv;
            const float* hp = g_h2 + (size_t)sq * C2;
            acc0 += a * hp[lane];
            if (lane < 8) acc1 += a * hp[32 + lane];
        }
    }

    out[(size_t)node * C2 + lane] = acc0 + b2[lane];
    if (lane < 8)
        out[(size_t)node * C2 + 32 + lane] = acc1 + b2[32 + lane];
}

// ============================================================================
// launch
// ============================================================================
extern "C" void kernel_launch(void* const* d_in, const int* in_sizes, int n_in,
                              void* d_out, int out_size)
{
    const float* feat = (const float*)d_in[0];
    const int*   src  = (const int*)  d_in[1];
    const int*   dst  = (const int*)  d_in[2];
    const float* W1   = (const float*)d_in[3];
    const float* al1  = (const float*)d_in[4];
    const float* ar1  = (const float*)d_in[5];
    const float* b1   = (const float*)d_in[6];
    const float* W2   = (const float*)d_in[7];
    const float* al2  = (const float*)d_in[8];
    const float* ar2  = (const float*)d_in[9];
    const float* b2   = (const float*)d_in[10];
    float* out = (float*)d_out;

    const int n = in_sizes[0] / INDIM;   // 100000
    const int e = in_sizes[1];           // 1600000

    float *p_h1 = 0, *p_out1 = 0, *p_h2 = 0, *p_W2p = 0;
    cudaGetSymbolAddress((void**)&p_h1,   g_h1);
    cudaGetSymbolAddress((void**)&p_out1, g_out1);
    cudaGetSymbolAddress((void**)&p_h2,   g_h2);
    cudaGetSymbolAddress((void**)&p_W2p,  g_W2p);

    const int TB = 256;
    const int nblk_scan = (n + 1023) / 1024;

    // ---- CSR build (shared by both layers) ----
    zero_deg<<<(n + TB - 1) / TB, TB>>>(n);
    count_kernel<<<(e + TB - 1) / TB, TB>>>(dst, e);
    scan_local<<<nblk_scan, 1024>>>(n);
    scan_part<<<1, 32>>>(nblk_scan, n);
    add_part<<<(n + TB - 1) / TB, TB>>>(n);
    scatter_kernel<<<(e + TB - 1) / TB, TB>>>(src, dst, e);

    pack_W2<<<(HID * C2P + TB - 1) / TB, TB>>>(W2);

    // ---- layer 1 ----
    gemm_tiled<INDIM, HID, HID><<<(n + 63) / 64, 256>>>(feat, W1, p_h1, n, HID);
    elr1_kernel<<<(n + 127) / 128, 128>>>(al1, ar1, n);
    gat1_kernel<<<(n * 32 + TB - 1) / TB, TB>>>(b1, n);

    // ---- layer 2 ----
    gemm_tiled<HID, C2P, C2><<<(n + 63) / 64, 256>>>(p_out1, p_W2p, p_h2, n, C2);
    elr2_kernel<<<(n + 127) / 128, 128>>>(al2, ar2, n);
    gat2_kernel<<<(n * 32 + TB - 1) / TB, TB>>>(out, b2, n);
}

// round 4
// speedup vs baseline: 2.0997x; 1.0684x over previous
#include <cuda_runtime.h>

// Problem constants (fixed by the dataset)
#define INDIM 256
#define HID   128     // H * F1
#define NH    4
#define FD    32
#define C2    40      // classes
#define C2P   64      // padded cols for gemm2
#define NMAXN 100000
#define EMAXE 1600000

#define NEG_INF __int_as_float(0xff800000)

// -------- scratch (static device globals; no allocations anywhere) --------
__device__ float g_h1  [(size_t)NMAXN * HID];   // layer1 projection
__device__ float g_out1[(size_t)NMAXN * HID];   // layer1 output (post-ELU)
__device__ float g_h2  [(size_t)NMAXN * C2];    // layer2 projection
__device__ float g_el1 [NMAXN * NH];
__device__ float g_er1 [NMAXN * NH];
__device__ float g_el2 [NMAXN];
__device__ float g_er2 [NMAXN];
__device__ float g_e1  [(size_t)EMAXE * NH];    // slow-path scratch only
__device__ float g_e2  [EMAXE];                 // slow-path scratch only
__device__ float g_W2p [HID * C2P];             // zero-padded W2 (128x64)
// CSR by dst
__device__ int   g_deg [NMAXN];
__device__ int   g_off [NMAXN + 1];
__device__ int   g_cur [NMAXN];
__device__ int   g_part[256];
__device__ int   g_csr_src[EMAXE];

// -------- helpers --------
__device__ __forceinline__ float lrelu(float v) { return v > 0.f ? v : 0.2f * v; }
__device__ __forceinline__ float elu(float v)   { return v > 0.f ? v : (__expf(v) - 1.f); }

// ============================================================================
// GEMM1: 128x128 tile, BK=16, 256 threads, 8x8 register blocking.
// A stored transposed in smem so both operands read via LDS.128.
// ============================================================================
template <int K>
__global__ __launch_bounds__(256)
void gemm128(const float* __restrict__ A, const float* __restrict__ W,
             float* __restrict__ C, int nrows)
{
    __shared__ float As[16][136];   // [k][row], padded
    __shared__ float Ws[16][128];   // [k][col]

    const int tid = threadIdx.x;
    const int tx  = tid & 15;       // col block: cols [tx*8, tx*8+8)
    const int ty  = tid >> 4;       // row block: rows [ty*8, ty*8+8)
    const int r0  = blockIdx.x * 128;

    float acc[8][8];
#pragma unroll
    for (int i = 0; i < 8; i++)
#pragma unroll
        for (int j = 0; j < 8; j++) acc[i][j] = 0.f;

    for (int kt = 0; kt < K; kt += 16) {
        // A tile: 128 rows x 16 k, transposed store
#pragma unroll
        for (int i = 0; i < 2; i++) {
            int idx = tid + i * 256;          // 0..511
            int r   = idx >> 2;               // 0..127
            int kq  = (idx & 3) * 4;          // 0,4,8,12
            float4 v = make_float4(0.f, 0.f, 0.f, 0.f);
            int row = r0 + r;
            if (row < nrows)
                v = *(const float4*)(A + (size_t)row * K + kt + kq);
            As[kq + 0][r] = v.x; As[kq + 1][r] = v.y;
            As[kq + 2][r] = v.z; As[kq + 3][r] = v.w;
        }
        // W tile: 16 k x 128 cols, direct copy
#pragma unroll
        for (int i = 0; i < 2; i++) {
            int idx = tid + i * 256;
            int kr  = idx >> 5;               // 0..15
            int cq  = (idx & 31) * 4;
            *(float4*)(&Ws[kr][cq]) =
                *(const float4*)(W + (size_t)(kt + kr) * 128 + cq);
        }
        __syncthreads();

#pragma unroll
        for (int k = 0; k < 16; k++) {
            float4 a0 = *(const float4*)(&As[k][ty * 8]);
            float4 a1 = *(const float4*)(&As[k][ty * 8 + 4]);
            float4 w0 = *(const float4*)(&Ws[k][tx * 8]);
            float4 w1 = *(const float4*)(&Ws[k][tx * 8 + 4]);
            float a[8] = {a0.x, a0.y, a0.z, a0.w, a1.x, a1.y, a1.z, a1.w};
            float w[8] = {w0.x, w0.y, w0.z, w0.w, w1.x, w1.y, w1.z, w1.w};
#pragma unroll
            for (int i = 0; i < 8; i++)
#pragma unroll
                for (int j = 0; j < 8; j++) acc[i][j] += a[i] * w[j];
        }
        __syncthreads();
    }

#pragma unroll
    for (int i = 0; i < 8; i++) {
        int row = r0 + ty * 8 + i;
        if (row >= nrows) continue;
        float* cp = C + (size_t)row * 128 + tx * 8;
        *(float4*)(cp)     = make_float4(acc[i][0], acc[i][1], acc[i][2], acc[i][3]);
        *(float4*)(cp + 4) = make_float4(acc[i][4], acc[i][5], acc[i][6], acc[i][7]);
    }
}

// ============================================================================
// GEMM2 (small): old tiled version, known good
// ============================================================================
template <int K, int NC, int NCREAL>
__global__ __launch_bounds__(256)
void gemm_tiled(const float* __restrict__ A, const float* __restrict__ W,
                float* __restrict__ C, int nrows, int ostride)
{
    constexpr int CPT = NC / 32;
    __shared__ float fsh[64][32];
    __shared__ float wsh[32][NC];

    const int tid = threadIdx.x;
    const int r0  = blockIdx.x * 64;
    const int cx  = tid & 31;
    const int ry  = tid >> 5;

    float acc[8][CPT];
#pragma unroll
    for (int i = 0; i < 8; i++)
#pragma unroll
        for (int j = 0; j < CPT; j++) acc[i][j] = 0.f;

    for (int kt = 0; kt < K; kt += 32) {
#pragma unroll
        for (int i = 0; i < 2; i++) {
            int idx = tid + i * 256;
            int r = idx >> 3, kq = idx & 7;
            int row = r0 + r;
            float4 v = make_float4(0.f, 0.f, 0.f, 0.f);
            if (row < nrows)
                v = *(const float4*)(A + (size_t)row * K + kt + kq * 4);
            *(float4*)(&fsh[r][kq * 4]) = v;
        }
#pragma unroll
        for (int i = 0; i < CPT; i++) {
            int idx = tid + i * 256;
            int kr = idx / (NC / 4), cq = idx % (NC / 4);
            *(float4*)(&wsh[kr][cq * 4]) =
                *(const float4*)(W + (size_t)(kt + kr) * NC + cq * 4);
        }
        __syncthreads();

#pragma unroll
        for (int k = 0; k < 32; k++) {
            float w[CPT];
            if constexpr (CPT == 4) {
                float4 wv = *(const float4*)(&wsh[k][cx * 4]);
                w[0] = wv.x; w[1] = wv.y; w[2] = wv.z; w[3] = wv.w;
            } else {
                float2 wv = *(const float2*)(&wsh[k][cx * 2]);
                w[0] = wv.x; w[1] = wv.y;
            }
#pragma unroll
            for (int i = 0; i < 8; i++) {
                float f = fsh[ry * 8 + i][k];
#pragma unroll
                for (int j = 0; j < CPT; j++) acc[i][j] += f * w[j];
            }
        }
        __syncthreads();
    }

#pragma unroll
    for (int i = 0; i < 8; i++) {
        int row = r0 + ry * 8 + i;
        if (row >= nrows) continue;
#pragma unroll
        for (int j = 0; j < CPT; j++) {
            int col = cx * CPT + j;
            if (col < NCREAL)
                C[(size_t)row * ostride + col] = acc[i][j];
        }
    }
}

// ============================================================================
// CSR build
// ============================================================================
__global__ void zero_deg(int n)
{
    int i = blockIdx.x * blockDim.x + threadIdx.x;
    if (i < n) g_deg[i] = 0;
}

__global__ void count_kernel(const int* __restrict__ dst, int e)
{
    int i = blockIdx.x * blockDim.x + threadIdx.x;
    if (i < e) atomicAdd(&g_deg[dst[i]], 1);
}

__global__ __launch_bounds__(1024)
void scan_local(int n)
{
    __shared__ int sh[1024];
    int t = threadIdx.x;
    int i = blockIdx.x * 1024 + t;
    int val = (i < n) ? g_deg[i] : 0;
    sh[t] = val;
    __syncthreads();
#pragma unroll
    for (int d = 1; d < 1024; d <<= 1) {
        int x = (t >= d) ? sh[t - d] : 0;
        __syncthreads();
        sh[t] += x;
        __syncthreads();
    }
    if (i < n) g_off[i] = sh[t] - val;
    if (t == 1023) g_part[blockIdx.x] = sh[1023];
}

__global__ void scan_part(int nblk, int n)
{
    if (threadIdx.x != 0 || blockIdx.x != 0) return;
    int run = 0;
    for (int b = 0; b < nblk; b++) {
        int v = g_part[b];
        g_part[b] = run;
        run += v;
    }
    g_off[n] = run;
}

__global__ void add_part(int n)
{
    int i = blockIdx.x * blockDim.x + threadIdx.x;
    if (i >= n) return;
    int o = g_off[i] + g_part[i >> 10];
    g_off[i] = o;
    g_cur[i] = o;
}

__global__ void scatter_kernel(const int* __restrict__ src, const int* __restrict__ dst, int e)
{
    int i = blockIdx.x * blockDim.x + threadIdx.x;
    if (i >= e) return;
    int d = dst[i];
    int pos = atomicAdd(&g_cur[d], 1);
    g_csr_src[pos] = src[i];
}

// ============================================================================
// misc
// ============================================================================
__global__ void pack_W2(const float* __restrict__ W2)
{
    int i = blockIdx.x * blockDim.x + threadIdx.x;
    if (i >= HID * C2P) return;
    int k = i / C2P, c = i % C2P;
    g_W2p[i] = (c < C2) ? W2[k * C2 + c] : 0.f;
}

__global__ void elr1_kernel(const float* __restrict__ al, const float* __restrict__ ar, int n)
{
    __shared__ float sal[HID], sar[HID];
    if (threadIdx.x < HID) { sal[threadIdx.x] = al[threadIdx.x]; sar[threadIdx.x] = ar[threadIdx.x]; }
    __syncthreads();
    int i = blockIdx.x * blockDim.x + threadIdx.x;
    if (i >= n) return;
    const float* hrow = g_h1 + (size_t)i * HID;
    float el[NH] = {0.f, 0.f, 0.f, 0.f}, er[NH] = {0.f, 0.f, 0.f, 0.f};
#pragma unroll
    for (int k = 0; k < HID; k++) {
        float v = hrow[k];
        int h = k >> 5;
        el[h] += v * sal[k];
        er[h] += v * sar[k];
    }
    *(float4*)(g_el1 + (size_t)i * 4) = make_float4(el[0], el[1], el[2], el[3]);
    *(float4*)(g_er1 + (size_t)i * 4) = make_float4(er[0], er[1], er[2], er[3]);
}

__global__ void elr2_kernel(const float* __restrict__ al, const float* __restrict__ ar, int n)
{
    __shared__ float sal[C2], sar[C2];
    if (threadIdx.x < C2) { sal[threadIdx.x] = al[threadIdx.x]; sar[threadIdx.x] = ar[threadIdx.x]; }
    __syncthreads();
    int i = blockIdx.x * blockDim.x + threadIdx.x;
    if (i >= n) return;
    const float* hrow = g_h2 + (size_t)i * C2;
    float el = 0.f, er = 0.f;
#pragma unroll
    for (int k = 0; k < C2; k++) {
        float v = hrow[k];
        el += v * sal[k];
        er += v * sar[k];
    }
    g_el2[i] = el;
    g_er2[i] = er;
}

// ============================================================================
// Layer 1: warp per node. Fast path (deg<=32): softmax fully in registers,
// (src, alpha) staged in smem for the gather loop. No g_e1 traffic.
// ============================================================================
__global__ __launch_bounds__(256)
void gat1_kernel(const float* __restrict__ b1, int n)
{
    __shared__ float s_alpha[8][32][4];
    __shared__ int   s_src[8][32];

    int w    = threadIdx.x >> 5;
    int node = (blockIdx.x * blockDim.x + threadIdx.x) >> 5;
    int lane = threadIdx.x & 31;
    if (node >= n) return;                    // warp-uniform

    int off = g_off[node];
    int deg = g_off[node + 1] - off;
    int head = lane >> 3;

    float4 erd = *(const float4*)(g_er1 + (size_t)node * 4);
    float4 acc = make_float4(0.f, 0.f, 0.f, 0.f);

    if (deg <= 32) {
        // ---- fast path: everything in registers ----
        bool valid = lane < deg;
        int s = 0;
        float4 e4 = make_float4(NEG_INF, NEG_INF, NEG_INF, NEG_INF);
        if (valid) {
            s = g_csr_src[off + lane];
            float4 a = *(const float4*)(g_el1 + (size_t)s * 4);
            e4.x = lrelu(a.x + erd.x); e4.y = lrelu(a.y + erd.y);
            e4.z = lrelu(a.z + erd.z); e4.w = lrelu(a.w + erd.w);
        }
        float4 mx = e4;
#pragma unroll
        for (int o = 16; o; o >>= 1) {
            mx.x = fmaxf(mx.x, __shfl_xor_sync(0xffffffffu, mx.x, o));
            mx.y = fmaxf(mx.y, __shfl_xor_sync(0xffffffffu, mx.y, o));
            mx.z = fmaxf(mx.z, __shfl_xor_sync(0xffffffffu, mx.z, o));
            mx.w = fmaxf(mx.w, __shfl_xor_sync(0xffffffffu, mx.w, o));
        }
        float4 ee = make_float4(0.f, 0.f, 0.f, 0.f);
        if (valid) {
            ee.x = __expf(e4.x - mx.x); ee.y = __expf(e4.y - mx.y);
            ee.z = __expf(e4.z - mx.z); ee.w = __expf(e4.w - mx.w);
        }
        float4 sm = ee;
#pragma unroll
        for (int o = 16; o; o >>= 1) {
            sm.x += __shfl_xor_sync(0xffffffffu, sm.x, o);
            sm.y += __shfl_xor_sync(0xffffffffu, sm.y, o);
            sm.z += __shfl_xor_sync(0xffffffffu, sm.z, o);
            sm.w += __shfl_xor_sync(0xffffffffu, sm.w, o);
        }
        float4 al4 = make_float4(0.f, 0.f, 0.f, 0.f);
        if (valid) {
            al4.x = ee.x / sm.x; al4.y = ee.y / sm.y;
            al4.z = ee.z / sm.z; al4.w = ee.w / sm.w;
        }
        s_src[w][lane] = s;
        *(float4*)(&s_alpha[w][lane][0]) = al4;
        __syncwarp();

        for (int q = 0; q < deg; q++) {
            int   sq = s_src[w][q];
            float a  = s_alpha[w][q][head];
            float4 hv = *(const float4*)(g_h1 + (size_t)sq * HID + lane * 4);
            acc.x += a * hv.x; acc.y += a * hv.y;
            acc.z += a * hv.z; acc.w += a * hv.w;
        }
    } else {
        // ---- slow path (deg > 32, ~1e-4 of nodes): 3-pass via g_e1 ----
        float4 mx = make_float4(NEG_INF, NEG_INF, NEG_INF, NEG_INF);
        for (int base = 0; base < deg; base += 32) {
            int j = base + lane;
            if (j < deg) {
                int s = g_csr_src[off + j];
                float4 a = *(const float4*)(g_el1 + (size_t)s * 4);
                float4 e4;
                e4.x = lrelu(a.x + erd.x); e4.y = lrelu(a.y + erd.y);
                e4.z = lrelu(a.z + erd.z); e4.w = lrelu(a.w + erd.w);
                *(float4*)(g_e1 + (size_t)(off + j) * 4) = e4;
                mx.x = fmaxf(mx.x, e4.x); mx.y = fmaxf(mx.y, e4.y);
                mx.z = fmaxf(mx.z, e4.z); mx.w = fmaxf(mx.w, e4.w);
            }
        }
#pragma unroll
        for (int o = 16; o; o >>= 1) {
            mx.x = fmaxf(mx.x, __shfl_xor_sync(0xffffffffu, mx.x, o));
            mx.y = fmaxf(mx.y, __shfl_xor_sync(0xffffffffu, mx.y, o));
            mx.z = fmaxf(mx.z, __shfl_xor_sync(0xffffffffu, mx.z, o));
            mx.w = fmaxf(mx.w, __shfl_xor_sync(0xffffffffu, mx.w, o));
        }
        float4 sm = make_float4(0.f, 0.f, 0.f, 0.f);
        for (int base = 0; base < deg; base += 32) {
            int j = base + lane;
            if (j < deg) {
                float4 e4 = *(const float4*)(g_e1 + (size_t)(off + j) * 4);
                e4.x = __expf(e4.x - mx.x); e4.y = __expf(e4.y - mx.y);
                e4.z = __expf(e4.z - mx.z); e4.w = __expf(e4.w - mx.w);
                *(float4*)(g_e1 + (size_t)(off + j) * 4) = e4;
                sm.x += e4.x; sm.y += e4.y; sm.z += e4.z; sm.w += e4.w;
            }
        }
#pragma unroll
        for (int o = 16; o; o >>= 1) {
            sm.x += __shfl_xor_sync(0xffffffffu, sm.x, o);
            sm.y += __shfl_xor_sync(0xffffffffu, sm.y, o);
            sm.z += __shfl_xor_sync(0xffffffffu, sm.z, o);
            sm.w += __shfl_xor_sync(0xffffffffu, sm.w, o);
        }
        float invh = 1.f / ((head == 0) ? sm.x : (head == 1) ? sm.y : (head == 2) ? sm.z : sm.w);

        for (int base = 0; base < deg; base += 32) {
            int cnt = min(32, deg - base);
            int j = base + lane;
            int s = 0;
            float4 ee = make_float4(0.f, 0.f, 0.f, 0.f);
            if (j < deg) {
                s = g_csr_src[off + j];
                ee = *(const float4*)(g_e1 + (size_t)(off + j) * 4);
            }
            s_src[w][lane] = s;
            *(float4*)(&s_alpha[w][lane][0]) = ee;
            __syncwarp();
            for (int q = 0; q < cnt; q++) {
                int   sq = s_src[w][q];
                float a  = s_alpha[w][q][head] * invh;
                float4 hv = *(const float4*)(g_h1 + (size_t)sq * HID + lane * 4);
                acc.x += a * hv.x; acc.y += a * hv.y;
                acc.z += a * hv.z; acc.w += a * hv.w;
            }
            __syncwarp();
        }
    }

    // epilogue: bias + ELU
    float4 bb = *(const float4*)(b1 + lane * 4);
    float4 o;
    o.x = elu(acc.x + bb.x); o.y = elu(acc.y + bb.y);
    o.z = elu(acc.z + bb.z); o.w = elu(acc.w + bb.w);
    *(float4*)(g_out1 + (size_t)node * HID + lane * 4) = o;
}

// ============================================================================
// Layer 2: warp per node, same structure (1 head, C=40)
// ============================================================================
__global__ __launch_bounds__(256)
void gat2_kernel(float* __restrict__ out, const float* __restrict__ b2, int n)
{
    __shared__ float s_a[8][32];
    __shared__ int   s_src[8][32];

    int w    = threadIdx.x >> 5;
    int node = (blockIdx.x * blockDim.x + threadIdx.x) >> 5;
    int lane = threadIdx.x & 31;
    if (node >= n) return;

    int off = g_off[node];
    int deg = g_off[node + 1] - off;
    float erd = g_er2[node];

    float acc0 = 0.f, acc1 = 0.f;

    if (deg <= 32) {
        bool valid = lane < deg;
        int s = 0;
        float e = NEG_INF;
        if (valid) {
            s = g_csr_src[off + lane];
            e = lrelu(g_el2[s] + erd);
        }
        float mx = e;
#pragma unroll
        for (int o = 16; o; o >>= 1)
            mx = fmaxf(mx, __shfl_xor_sync(0xffffffffu, mx, o));
        float ee = valid ? __expf(e - mx) : 0.f;
        float sm = ee;
#pragma unroll
        for (int o = 16; o; o >>= 1)
            sm += __shfl_xor_sync(0xffffffffu, sm, o);
        float alpha = valid ? (ee / sm) : 0.f;

        s_src[w][lane] = s;
        s_a[w][lane] = alpha;
        __syncwarp();

        for (int q = 0; q < deg; q++) {
            int   sq = s_src[w][q];
            float a  = s_a[w][q];
            const float* hp = g_h2 + (size_t)sq * C2;
            acc0 += a * hp[lane];
            if (lane < 8) acc1 += a * hp[32 + lane];
        }
    } else {
        float mx = NEG_INF;
        for (int base = 0; base < deg; base += 32) {
            int j = base + lane;
            if (j < deg) {
                int s = g_csr_src[off + j];
                float e = lrelu(g_el2[s] + erd);
                g_e2[off + j] = e;
                mx = fmaxf(mx, e);
            }
        }
#pragma unroll
        for (int o = 16; o; o >>= 1)
            mx = fmaxf(mx, __shfl_xor_sync(0xffffffffu, mx, o));
        float sm = 0.f;
        for (int base = 0; base < deg; base += 32) {
            int j = base + lane;
            if (j < deg) {
                float ee = __expf(g_e2[off + j] - mx);
                g_e2[off + j] = ee;
                sm += ee;
            }
        }
#pragma unroll
        for (int o = 16; o; o >>= 1)
            sm += __shfl_xor_sync(0xffffffffu, sm, o);
        float inv = 1.f / sm;

        for (int base = 0; base < deg; base += 32) {
            int cnt = min(32, deg - base);
            int j = base + lane;
            int s = 0; float ee = 0.f;
            if (j < deg) {
                s = g_csr_src[off + j];
                ee = g_e2[off + j];
            }
            s_src[w][lane] = s;
            s_a[w][lane] = ee * inv;
            __syncwarp();
            for (int q = 0; q < cnt; q++) {
                int   sq = s_src[w][q];
                float a  = s_a[w][q];
                const float* hp = g_h2 + (size_t)sq * C2;
                acc0 += a * hp[lane];
                if (lane < 8) acc1 += a * hp[32 + lane];
            }
            __syncwarp();
        }
    }

    out[(size_t)node * C2 + lane] = acc0 + b2[lane];
    if (lane < 8)
        out[(size_t)node * C2 + 32 + lane] = acc1 + b2[32 + lane];
}

// ============================================================================
// launch
// ============================================================================
extern "C" void kernel_launch(void* const* d_in, const int* in_sizes, int n_in,
                              void* d_out, int out_size)
{
    const float* feat = (const float*)d_in[0];
    const int*   src  = (const int*)  d_in[1];
    const int*   dst  = (const int*)  d_in[2];
    const float* W1   = (const float*)d_in[3];
    const float* al1  = (const float*)d_in[4];
    const float* ar1  = (const float*)d_in[5];
    const float* b1   = (const float*)d_in[6];
    const float* W2   = (const float*)d_in[7];
    const float* al2  = (const float*)d_in[8];
    const float* ar2  = (const float*)d_in[9];
    const float* b2   = (const float*)d_in[10];
    float* out = (float*)d_out;

    const int n = in_sizes[0] / INDIM;   // 100000
    const int e = in_sizes[1];           // 1600000

    float *p_h1 = 0, *p_out1 = 0, *p_h2 = 0, *p_W2p = 0;
    cudaGetSymbolAddress((void**)&p_h1,   g_h1);
    cudaGetSymbolAddress((void**)&p_out1, g_out1);
    cudaGetSymbolAddress((void**)&p_h2,   g_h2);
    cudaGetSymbolAddress((void**)&p_W2p,  g_W2p);

    const int TB = 256;
    const int nblk_scan = (n + 1023) / 1024;

    // ---- CSR build (shared by both layers) ----
    zero_deg<<<(n + TB - 1) / TB, TB>>>(n);
    count_kernel<<<(e + TB - 1) / TB, TB>>>(dst, e);
    scan_local<<<nblk_scan, 1024>>>(n);
    scan_part<<<1, 32>>>(nblk_scan, n);
    add_part<<<(n + TB - 1) / TB, TB>>>(n);
    scatter_kernel<<<(e + TB - 1) / TB, TB>>>(src, dst, e);

    pack_W2<<<(HID * C2P + TB - 1) / TB, TB>>>(W2);

    // ---- layer 1 ----
    gemm128<INDIM><<<(n + 127) / 128, 256>>>(feat, W1, p_h1, n);
    elr1_kernel<<<(n + 127) / 128, 128>>>(al1, ar1, n);
    gat1_kernel<<<(n * 32 + TB - 1) / TB, TB>>>(b1, n);

    // ---- layer 2 ----
    gemm_tiled<HID, C2P, C2><<<(n + 63) / 64, 256>>>(p_out1, p_W2p, p_h2, n, C2);
    elr2_kernel<<<(n + 127) / 128, 128>>>(al2, ar2, n);
    gat2_kernel<<<(n * 32 + TB - 1) / TB, TB>>>(out, b2, n);
}

// round 5
// speedup vs baseline: 2.5294x; 1.2047x over previous
#include <cuda_runtime.h>

// Problem constants (fixed by the dataset)
#define INDIM 256
#define HID   128     // H * F1
#define NH    4
#define FD    32
#define C2    40      // classes
#define C2P   64      // padded cols for gemm2
#define NMAXN 100000
#define EMAXE 1600000

#define NEG_INF __int_as_float(0xff800000)

// -------- scratch (static device globals; no allocations anywhere) --------
__device__ float g_h1  [(size_t)NMAXN * HID];   // layer1 projection
__device__ float g_out1[(size_t)NMAXN * HID];   // layer1 output (post-ELU)
__device__ float g_h2  [(size_t)NMAXN * C2];    // layer2 projection
__device__ float g_el1 [NMAXN * NH];
__device__ float g_er1 [NMAXN * NH];
__device__ float g_el2 [NMAXN];
__device__ float g_er2 [NMAXN];
__device__ float g_e1  [(size_t)EMAXE * NH];    // slow-path scratch only
__device__ float g_e2  [EMAXE];                 // slow-path scratch only
__device__ float g_W2p [HID * C2P];             // zero-padded W2 (128x64)
// CSR by dst
__device__ int   g_deg [NMAXN];
__device__ int   g_off [NMAXN + 1];
__device__ int   g_cur [NMAXN];
__device__ int   g_part[256];
__device__ int   g_csr_src[EMAXE];

// -------- helpers --------
__device__ __forceinline__ float lrelu(float v) { return v > 0.f ? v : 0.2f * v; }
__device__ __forceinline__ float elu(float v)   { return v > 0.f ? v : (__expf(v) - 1.f); }

// ============================================================================
// GEMM1 + fused elr1: 128x128 tile, BK=16, 256 threads, 8x8 register blocking.
// Epilogue computes per-row, per-head el/er directly from acc registers.
// ============================================================================
template <int K>
__global__ __launch_bounds__(256)
void gemm128_elr(const float* __restrict__ A, const float* __restrict__ W,
                 float* __restrict__ C,
                 const float* __restrict__ al, const float* __restrict__ ar,
                 int nrows)
{
    __shared__ float As[16][136];   // [k][row], padded
    __shared__ float Ws[16][128];   // [k][col]

    const int tid = threadIdx.x;
    const int tx  = tid & 15;       // col block: cols [tx*8, tx*8+8)
    const int ty  = tid >> 4;       // row block: rows [ty*8, ty*8+8)
    const int r0  = blockIdx.x * 128;

    float acc[8][8];
#pragma unroll
    for (int i = 0; i < 8; i++)
#pragma unroll
        for (int j = 0; j < 8; j++) acc[i][j] = 0.f;

    for (int kt = 0; kt < K; kt += 16) {
#pragma unroll
        for (int i = 0; i < 2; i++) {
            int idx = tid + i * 256;
            int r   = idx >> 2;
            int kq  = (idx & 3) * 4;
            float4 v = make_float4(0.f, 0.f, 0.f, 0.f);
            int row = r0 + r;
            if (row < nrows)
                v = *(const float4*)(A + (size_t)row * K + kt + kq);
            As[kq + 0][r] = v.x; As[kq + 1][r] = v.y;
            As[kq + 2][r] = v.z; As[kq + 3][r] = v.w;
        }
#pragma unroll
        for (int i = 0; i < 2; i++) {
            int idx = tid + i * 256;
            int kr  = idx >> 5;
            int cq  = (idx & 31) * 4;
            *(float4*)(&Ws[kr][cq]) =
                *(const float4*)(W + (size_t)(kt + kr) * 128 + cq);
        }
        __syncthreads();

#pragma unroll
        for (int k = 0; k < 16; k++) {
            float4 a0 = *(const float4*)(&As[k][ty * 8]);
            float4 a1 = *(const float4*)(&As[k][ty * 8 + 4]);
            float4 w0 = *(const float4*)(&Ws[k][tx * 8]);
            float4 w1 = *(const float4*)(&Ws[k][tx * 8 + 4]);
            float a[8] = {a0.x, a0.y, a0.z, a0.w, a1.x, a1.y, a1.z, a1.w};
            float w[8] = {w0.x, w0.y, w0.z, w0.w, w1.x, w1.y, w1.z, w1.w};
#pragma unroll
            for (int i = 0; i < 8; i++)
#pragma unroll
                for (int j = 0; j < 8; j++) acc[i][j] += a[i] * w[j];
        }
        __syncthreads();
    }

    // store C
#pragma unroll
    for (int i = 0; i < 8; i++) {
        int row = r0 + ty * 8 + i;
        if (row >= nrows) continue;
        float* cp = C + (size_t)row * 128 + tx * 8;
        *(float4*)(cp)     = make_float4(acc[i][0], acc[i][1], acc[i][2], acc[i][3]);
        *(float4*)(cp + 4) = make_float4(acc[i][4], acc[i][5], acc[i][6], acc[i][7]);
    }

    // fused elr1: this thread's 8 cols belong to head (tx>>2); reduce over the
    // 4 tx-threads of that head (xor 1,2 — stays in 16-lane half / same ty).
    const int lane = tid & 31;
    float alv[8], arv[8];
#pragma unroll
    for (int j = 0; j < 8; j++) {
        alv[j] = al[tx * 8 + j];
        arv[j] = ar[tx * 8 + j];
    }
    const int head = (lane & 15) >> 2;
#pragma unroll
    for (int i = 0; i < 8; i++) {
        float pel = 0.f, per = 0.f;
#pragma unroll
        for (int j = 0; j < 8; j++) {
            pel += acc[i][j] * alv[j];
            per += acc[i][j] * arv[j];
        }
        pel += __shfl_xor_sync(0xffffffffu, pel, 1);
        pel += __shfl_xor_sync(0xffffffffu, pel, 2);
        per += __shfl_xor_sync(0xffffffffu, per, 1);
        per += __shfl_xor_sync(0xffffffffu, per, 2);
        int row = r0 + ty * 8 + i;
        if ((lane & 3) == 0 && row < nrows) {
            g_el1[row * 4 + head] = pel;
            g_er1[row * 4 + head] = per;
        }
    }
}

// ============================================================================
// GEMM2 + fused elr2: 64-row tile, NC=64 padded (CPT=2)
// ============================================================================
template <int K, int NC, int NCREAL>
__global__ __launch_bounds__(256)
void gemm_tiled_elr(const float* __restrict__ A, const float* __restrict__ W,
                    float* __restrict__ C,
                    const float* __restrict__ al, const float* __restrict__ ar,
                    int nrows, int ostride)
{
    constexpr int CPT = NC / 32;     // 2
    __shared__ float fsh[64][32];
    __shared__ float wsh[32][NC];

    const int tid = threadIdx.x;
    const int r0  = blockIdx.x * 64;
    const int cx  = tid & 31;
    const int ry  = tid >> 5;

    float acc[8][CPT];
#pragma unroll
    for (int i = 0; i < 8; i++)
#pragma unroll
        for (int j = 0; j < CPT; j++) acc[i][j] = 0.f;

    for (int kt = 0; kt < K; kt += 32) {
#pragma unroll
        for (int i = 0; i < 2; i++) {
            int idx = tid + i * 256;
            int r = idx >> 3, kq = idx & 7;
            int row = r0 + r;
            float4 v = make_float4(0.f, 0.f, 0.f, 0.f);
            if (row < nrows)
                v = *(const float4*)(A + (size_t)row * K + kt + kq * 4);
            *(float4*)(&fsh[r][kq * 4]) = v;
        }
#pragma unroll
        for (int i = 0; i < CPT; i++) {
            int idx = tid + i * 256;
            int kr = idx / (NC / 4), cq = idx % (NC / 4);
            *(float4*)(&wsh[kr][cq * 4]) =
                *(const float4*)(W + (size_t)(kt + kr) * NC + cq * 4);
        }
        __syncthreads();

#pragma unroll
        for (int k = 0; k < 32; k++) {
            float2 wv = *(const float2*)(&wsh[k][cx * 2]);
#pragma unroll
            for (int i = 0; i < 8; i++) {
                float f = fsh[ry * 8 + i][k];
                acc[i][0] += f * wv.x;
                acc[i][1] += f * wv.y;
            }
        }
        __syncthreads();
    }

    // attention vector entries for this thread's 2 cols (0 beyond NCREAL)
    int c0 = cx * 2, c1 = cx * 2 + 1;
    float al0 = (c0 < NCREAL) ? al[c0] : 0.f;
    float al1v = (c1 < NCREAL) ? al[c1] : 0.f;
    float ar0 = (c0 < NCREAL) ? ar[c0] : 0.f;
    float ar1v = (c1 < NCREAL) ? ar[c1] : 0.f;

#pragma unroll
    for (int i = 0; i < 8; i++) {
        int row = r0 + ry * 8 + i;
        bool ok = row < nrows;
        if (ok) {
            if (c0 < NCREAL) C[(size_t)row * ostride + c0] = acc[i][0];
            if (c1 < NCREAL) C[(size_t)row * ostride + c1] = acc[i][1];
        }
        // fused elr2: full-warp reduce (all lanes in warp share this row)
        float pel = acc[i][0] * al0 + acc[i][1] * al1v;
        float per = acc[i][0] * ar0 + acc[i][1] * ar1v;
#pragma unroll
        for (int o = 16; o; o >>= 1) {
            pel += __shfl_xor_sync(0xffffffffu, pel, o);
            per += __shfl_xor_sync(0xffffffffu, per, o);
        }
        if (cx == 0 && ok) {
            g_el2[row] = pel;
            g_er2[row] = per;
        }
    }
}

// ============================================================================
// CSR build
// ============================================================================
__global__ void zero_deg(int n)
{
    int i = blockIdx.x * blockDim.x + threadIdx.x;
    if (i < n) g_deg[i] = 0;
}

__global__ void count_kernel(const int* __restrict__ dst, int e)
{
    int i = blockIdx.x * blockDim.x + threadIdx.x;
    if (i < e) atomicAdd(&g_deg[dst[i]], 1);
}

__global__ __launch_bounds__(1024)
void scan_local(int n)
{
    __shared__ int sh[1024];
    int t = threadIdx.x;
    int i = blockIdx.x * 1024 + t;
    int val = (i < n) ? g_deg[i] : 0;
    sh[t] = val;
    __syncthreads();
#pragma unroll
    for (int d = 1; d < 1024; d <<= 1) {
        int x = (t >= d) ? sh[t - d] : 0;
        __syncthreads();
        sh[t] += x;
        __syncthreads();
    }
    if (i < n) g_off[i] = sh[t] - val;
    if (t == 1023) g_part[blockIdx.x] = sh[1023];
}

__global__ void scan_part(int nblk, int n)
{
    if (threadIdx.x != 0 || blockIdx.x != 0) return;
    int run = 0;
    for (int b = 0; b < nblk; b++) {
        int v = g_part[b];
        g_part[b] = run;
        run += v;
    }
    g_off[n] = run;
}

__global__ void add_part(int n)
{
    int i = blockIdx.x * blockDim.x + threadIdx.x;
    if (i >= n) return;
    int o = g_off[i] + g_part[i >> 10];
    g_off[i] = o;
    g_cur[i] = o;
}

__global__ void scatter_kernel(const int* __restrict__ src, const int* __restrict__ dst, int e)
{
    int i = blockIdx.x * blockDim.x + threadIdx.x;
    if (i >= e) return;
    int d = dst[i];
    int pos = atomicAdd(&g_cur[d], 1);
    g_csr_src[pos] = src[i];
}

__global__ void pack_W2(const float* __restrict__ W2)
{
    int i = blockIdx.x * blockDim.x + threadIdx.x;
    if (i >= HID * C2P) return;
    int k = i / C2P, c = i % C2P;
    g_W2p[i] = (c < C2) ? W2[k * C2 + c] : 0.f;
}

// ============================================================================
// Layer 1: warp per node (fast path deg<=32 in registers)
// ============================================================================
__global__ __launch_bounds__(256)
void gat1_kernel(const float* __restrict__ b1, int n)
{
    __shared__ float s_alpha[8][32][4];
    __shared__ int   s_src[8][32];

    int w    = threadIdx.x >> 5;
    int node = (blockIdx.x * blockDim.x + threadIdx.x) >> 5;
    int lane = threadIdx.x & 31;
    if (node >= n) return;

    int off = g_off[node];
    int deg = g_off[node + 1] - off;
    int head = lane >> 3;

    float4 erd = *(const float4*)(g_er1 + (size_t)node * 4);
    float4 acc = make_float4(0.f, 0.f, 0.f, 0.f);

    if (deg <= 32) {
        bool valid = lane < deg;
        int s = 0;
        float4 e4 = make_float4(NEG_INF, NEG_INF, NEG_INF, NEG_INF);
        if (valid) {
            s = g_csr_src[off + lane];
            float4 a = *(const float4*)(g_el1 + (size_t)s * 4);
            e4.x = lrelu(a.x + erd.x); e4.y = lrelu(a.y + erd.y);
            e4.z = lrelu(a.z + erd.z); e4.w = lrelu(a.w + erd.w);
        }
        float4 mx = e4;
#pragma unroll
        for (int o = 16; o; o >>= 1) {
            mx.x = fmaxf(mx.x, __shfl_xor_sync(0xffffffffu, mx.x, o));
            mx.y = fmaxf(mx.y, __shfl_xor_sync(0xffffffffu, mx.y, o));
            mx.z = fmaxf(mx.z, __shfl_xor_sync(0xffffffffu, mx.z, o));
            mx.w = fmaxf(mx.w, __shfl_xor_sync(0xffffffffu, mx.w, o));
        }
        float4 ee = make_float4(0.f, 0.f, 0.f, 0.f);
        if (valid) {
            ee.x = __expf(e4.x - mx.x); ee.y = __expf(e4.y - mx.y);
            ee.z = __expf(e4.z - mx.z); ee.w = __expf(e4.w - mx.w);
        }
        float4 sm = ee;
#pragma unroll
        for (int o = 16; o; o >>= 1) {
            sm.x += __shfl_xor_sync(0xffffffffu, sm.x, o);
            sm.y += __shfl_xor_sync(0xffffffffu, sm.y, o);
            sm.z += __shfl_xor_sync(0xffffffffu, sm.z, o);
            sm.w += __shfl_xor_sync(0xffffffffu, sm.w, o);
        }
        float4 al4 = make_float4(0.f, 0.f, 0.f, 0.f);
        if (valid) {
            al4.x = ee.x / sm.x; al4.y = ee.y / sm.y;
            al4.z = ee.z / sm.z; al4.w = ee.w / sm.w;
        }
        s_src[w][lane] = s;
        *(float4*)(&s_alpha[w][lane][0]) = al4;
        __syncwarp();

        for (int q = 0; q < deg; q++) {
            int   sq = s_src[w][q];
            float a  = s_alpha[w][q][head];
            float4 hv = *(const float4*)(g_h1 + (size_t)sq * HID + lane * 4);
            acc.x += a * hv.x; acc.y += a * hv.y;
            acc.z += a * hv.z; acc.w += a * hv.w;
        }
    } else {
        float4 mx = make_float4(NEG_INF, NEG_INF, NEG_INF, NEG_INF);
        for (int base = 0; base < deg; base += 32) {
            int j = base + lane;
            if (j < deg) {
                int s = g_csr_src[off + j];
                float4 a = *(const float4*)(g_el1 + (size_t)s * 4);
                float4 e4;
                e4.x = lrelu(a.x + erd.x); e4.y = lrelu(a.y + erd.y);
                e4.z = lrelu(a.z + erd.z); e4.w = lrelu(a.w + erd.w);
                *(float4*)(g_e1 + (size_t)(off + j) * 4) = e4;
                mx.x = fmaxf(mx.x, e4.x); mx.y = fmaxf(mx.y, e4.y);
                mx.z = fmaxf(mx.z, e4.z); mx.w = fmaxf(mx.w, e4.w);
            }
        }
#pragma unroll
        for (int o = 16; o; o >>= 1) {
            mx.x = fmaxf(mx.x, __shfl_xor_sync(0xffffffffu, mx.x, o));
            mx.y = fmaxf(mx.y, __shfl_xor_sync(0xffffffffu, mx.y, o));
            mx.z = fmaxf(mx.z, __shfl_xor_sync(0xffffffffu, mx.z, o));
            mx.w = fmaxf(mx.w, __shfl_xor_sync(0xffffffffu, mx.w, o));
        }
        float4 sm = make_float4(0.f, 0.f, 0.f, 0.f);
        for (int base = 0; base < deg; base += 32) {
            int j = base + lane;
            if (j < deg) {
                float4 e4 = *(const float4*)(g_e1 + (size_t)(off + j) * 4);
                e4.x = __expf(e4.x - mx.x); e4.y = __expf(e4.y - mx.y);
                e4.z = __expf(e4.z - mx.z); e4.w = __expf(e4.w - mx.w);
                *(float4*)(g_e1 + (size_t)(off + j) * 4) = e4;
                sm.x += e4.x; sm.y += e4.y; sm.z += e4.z; sm.w += e4.w;
            }
        }
#pragma unroll
        for (int o = 16; o; o >>= 1) {
            sm.x += __shfl_xor_sync(0xffffffffu, sm.x, o);
            sm.y += __shfl_xor_sync(0xffffffffu, sm.y, o);
            sm.z += __shfl_xor_sync(0xffffffffu, sm.z, o);
            sm.w += __shfl_xor_sync(0xffffffffu, sm.w, o);
        }
        float invh = 1.f / ((head == 0) ? sm.x : (head == 1) ? sm.y : (head == 2) ? sm.z : sm.w);

        for (int base = 0; base < deg; base += 32) {
            int cnt = min(32, deg - base);
            int j = base + lane;
            int s = 0;
            float4 ee = make_float4(0.f, 0.f, 0.f, 0.f);
            if (j < deg) {
                s = g_csr_src[off + j];
                ee = *(const float4*)(g_e1 + (size_t)(off + j) * 4);
            }
            s_src[w][lane] = s;
            *(float4*)(&s_alpha[w][lane][0]) = ee;
            __syncwarp();
            for (int q = 0; q < cnt; q++) {
                int   sq = s_src[w][q];
                float a  = s_alpha[w][q][head] * invh;
                float4 hv = *(const float4*)(g_h1 + (size_t)sq * HID + lane * 4);
                acc.x += a * hv.x; acc.y += a * hv.y;
                acc.z += a * hv.z; acc.w += a * hv.w;
            }
            __syncwarp();
        }
    }

    float4 bb = *(const float4*)(b1 + lane * 4);
    float4 o;
    o.x = elu(acc.x + bb.x); o.y = elu(acc.y + bb.y);
    o.z = elu(acc.z + bb.z); o.w = elu(acc.w + bb.w);
    *(float4*)(g_out1 + (size_t)node * HID + lane * 4) = o;
}

// ============================================================================
// Layer 2: warp per node (1 head, C=40)
// ============================================================================
__global__ __launch_bounds__(256)
void gat2_kernel(float* __restrict__ out, const float* __restrict__ b2, int n)
{
    __shared__ float s_a[8][32];
    __shared__ int   s_src[8][32];

    int w    = threadIdx.x >> 5;
    int node = (blockIdx.x * blockDim.x + threadIdx.x) >> 5;
    int lane = threadIdx.x & 31;
    if (node >= n) return;

    int off = g_off[node];
    int deg = g_off[node + 1] - off;
    float erd = g_er2[node];

    float acc0 = 0.f, acc1 = 0.f;

    if (deg <= 32) {
        bool valid = lane < deg;
        int s = 0;
        float e = NEG_INF;
        if (valid) {
            s = g_csr_src[off + lane];
            e = lrelu(g_el2[s] + erd);
        }
        float mx = e;
#pragma unroll
        for (int o = 16; o; o >>= 1)
            mx = fmaxf(mx, __shfl_xor_sync(0xffffffffu, mx, o));
        float ee = valid ? __expf(e - mx) : 0.f;
        float sm = ee;
#pragma unroll
        for (int o = 16; o; o >>= 1)
            sm += __shfl_xor_sync(0xffffffffu, sm, o);
        float alpha = valid ? (ee / sm) : 0.f;

        s_src[w][lane] = s;
        s_a[w][lane] = alpha;
        __syncwarp();

        for (int q = 0; q < deg; q++) {
            int   sq = s_src[w][q];
            float a  = s_a[w][q];
            const float* hp = g_h2 + (size_t)sq * C2;
            acc0 += a * hp[lane];
            if (lane < 8) acc1 += a * hp[32 + lane];
        }
    } else {
        float mx = NEG_INF;
        for (int base = 0; base < deg; base += 32) {
            int j = base + lane;
            if (j < deg) {
                int s = g_csr_src[off + j];
                float e = lrelu(g_el2[s] + erd);
                g_e2[off + j] = e;
                mx = fmaxf(mx, e);
            }
        }
#pragma unroll
        for (int o = 16; o; o >>= 1)
            mx = fmaxf(mx, __shfl_xor_sync(0xffffffffu, mx, o));
        float sm = 0.f;
        for (int base = 0; base < deg; base += 32) {
            int j = base + lane;
            if (j < deg) {
                float ee = __expf(g_e2[off + j] - mx);
                g_e2[off + j] = ee;
                sm += ee;
            }
        }
#pragma unroll
        for (int o = 16; o; o >>= 1)
            sm += __shfl_xor_sync(0xffffffffu, sm, o);
        float inv = 1.f / sm;

        for (int base = 0; base < deg; base += 32) {
            int cnt = min(32, deg - base);
            int j = base + lane;
            int s = 0; float ee = 0.f;
            if (j < deg) {
                s = g_csr_src[off + j];
                ee = g_e2[off + j];
            }
            s_src[w][lane] = s;
            s_a[w][lane] = ee * inv;
            __syncwarp();
            for (int q = 0; q < cnt; q++) {
                int   sq = s_src[w][q];
                float a  = s_a[w][q];
                const float* hp = g_h2 + (size_t)sq * C2;
                acc0 += a * hp[lane];
                if (lane < 8) acc1 += a * hp[32 + lane];
            }
            __syncwarp();
        }
    }

    out[(size_t)node * C2 + lane] = acc0 + b2[lane];
    if (lane < 8)
        out[(size_t)node * C2 + 32 + lane] = acc1 + b2[32 + lane];
}

// ============================================================================
// launch — CSR build overlapped with gemm1 on a second stream
// ============================================================================
extern "C" void kernel_launch(void* const* d_in, const int* in_sizes, int n_in,
                              void* d_out, int out_size)
{
    const float* feat = (const float*)d_in[0];
    const int*   src  = (const int*)  d_in[1];
    const int*   dst  = (const int*)  d_in[2];
    const float* W1   = (const float*)d_in[3];
    const float* al1  = (const float*)d_in[4];
    const float* ar1  = (const float*)d_in[5];
    const float* b1   = (const float*)d_in[6];
    const float* W2   = (const float*)d_in[7];
    const float* al2  = (const float*)d_in[8];
    const float* ar2  = (const float*)d_in[9];
    const float* b2   = (const float*)d_in[10];
    float* out = (float*)d_out;

    const int n = in_sizes[0] / INDIM;   // 100000
    const int e = in_sizes[1];           // 1600000

    float *p_h1 = 0, *p_out1 = 0, *p_h2 = 0, *p_W2p = 0;
    cudaGetSymbolAddress((void**)&p_h1,   g_h1);
    cudaGetSymbolAddress((void**)&p_out1, g_out1);
    cudaGetSymbolAddress((void**)&p_h2,   g_h2);
    cudaGetSymbolAddress((void**)&p_W2p,  g_W2p);

    // side stream + events, created once (outside capture on first call;
    // reused deterministically — same launches every call)
    static cudaStream_t s2 = 0;
    static cudaEvent_t ev_fork = 0, ev_join = 0;
    if (!s2) {
        cudaStreamCreateWithFlags(&s2, cudaStreamNonBlocking);
        cudaEventCreateWithFlags(&ev_fork, cudaEventDisableTiming);
        cudaEventCreateWithFlags(&ev_join, cudaEventDisableTiming);
    }

    const int TB = 256;
    const int nblk_scan = (n + 1023) / 1024;

    // fork: CSR build + pack_W2 on s2, concurrent with gemm1 on default stream
    cudaEventRecord(ev_fork, 0);
    cudaStreamWaitEvent(s2, ev_fork, 0);

    zero_deg<<<(n + TB - 1) / TB, TB, 0, s2>>>(n);
    count_kernel<<<(e + TB - 1) / TB, TB, 0, s2>>>(dst, e);
    scan_local<<<nblk_scan, 1024, 0, s2>>>(n);
    scan_part<<<1, 32, 0, s2>>>(nblk_scan, n);
    add_part<<<(n + TB - 1) / TB, TB, 0, s2>>>(n);
    scatter_kernel<<<(e + TB - 1) / TB, TB, 0, s2>>>(src, dst, e);
    pack_W2<<<(HID * C2P + TB - 1) / TB, TB, 0, s2>>>(W2);
    cudaEventRecord(ev_join, s2);

    // default stream: layer-1 projection (+fused elr1)
    gemm128_elr<INDIM><<<(n + 127) / 128, 256>>>(feat, W1, p_h1, al1, ar1, n);

    // join
    cudaStreamWaitEvent(0, ev_join, 0);

    // layer-1 attention/aggregation
    gat1_kernel<<<(n * 32 + TB - 1) / TB, TB>>>(b1, n);

    // layer 2 (gemm + fused elr2, then attention/aggregation)
    gemm_tiled_elr<HID, C2P, C2><<<(n + 63) / 64, 256>>>(p_out1, p_W2p, p_h2, al2, ar2, n, C2);
    gat2_kernel<<<(n * 32 + TB - 1) / TB, TB>>>(out, b2, n);
}